// round 1
// baseline (speedup 1.0000x reference)
#include <cuda_runtime.h>
#include <math.h>

// ---------------- problem dims ----------------
#define T_STEPS 32
#define BATCH   64
#define TB      2048          // T*B
#define DIN     512
#define HID     512
#define G3      1536          // 3*HID
#define FEAT    768
#define VOCAB   32000
#define NT_G5   250           // VOCAB/128 n-tiles in out gemm

typedef unsigned long long u64;

// ---------------- scratch (static device globals; no allocs allowed) --------
__device__ float g_yemb[TB * DIN];
__device__ float g_ct[BATCH * HID];
__device__ float g_gi[TB * G3];
__device__ float g_h1[TB * HID];
__device__ float g_x[TB * HID];
__device__ float g_q[TB * HID];
__device__ float g_k[TB * HID];
__device__ float g_v[TB * HID];
__device__ float g_att[TB * HID];
__device__ float g_h2[TB * HID];
__device__ float g_logit[TB * DIN];
__device__ float g_part[TB * NT_G5];

// ---------------- f32x2 packed-FMA helpers (sm_100+) ----------------
__device__ __forceinline__ u64 f2pack(float x, float y) {
    u64 r;
    asm("mov.b64 %0, {%1, %2};" : "=l"(r) : "f"(x), "f"(y));
    return r;
}
__device__ __forceinline__ void f2unpack(u64 p, float& x, float& y) {
    asm("mov.b64 {%0, %1}, %2;" : "=f"(x), "=f"(y) : "l"(p));
}
__device__ __forceinline__ u64 ffma2(u64 a, u64 b, u64 c) {
    u64 d;
    asm("fma.rn.f32x2 %0, %1, %2, %3;" : "=l"(d) : "l"(a), "l"(b), "l"(c));
    return d;
}

// ---------------- embedding gather: g_yemb[row] = emb_W[y[row]] -------------
__global__ void k_gather(const int* __restrict__ y, const float* __restrict__ embW) {
    int row = blockIdx.x;
    int yi  = y[row];
    const float4* src = (const float4*)(embW + (size_t)yi * DIN);
    float4* dst = (float4*)(g_yemb + (size_t)row * DIN);
    dst[threadIdx.x] = src[threadIdx.x];   // 128 threads * float4 = 512 floats
}

// ---------------- generic fp32 GEMM: C[M,N] = act(A[M,K] @ B[N,K]^T + bias) -
// 64x64 tile, 256 threads, 4x4 microtile
template <bool TANH>
__global__ void k_gemm_nt(const float* __restrict__ A, const float* __restrict__ B,
                          const float* __restrict__ bias, float* __restrict__ C,
                          int M, int N, int K) {
    __shared__ float As[16][68];
    __shared__ float Bs[16][68];
    int m0 = blockIdx.y * 64, n0 = blockIdx.x * 64;
    int tid = threadIdx.x;
    int kk = tid & 15, rr = tid >> 4;   // rr: 0..15
    float c[4][4] = {};

    for (int k0 = 0; k0 < K; k0 += 16) {
        __syncthreads();
#pragma unroll
        for (int p = 0; p < 4; p++) {
            int m = rr + p * 16;
            As[kk][m] = (m0 + m < M) ? A[(size_t)(m0 + m) * K + k0 + kk] : 0.f;
            Bs[kk][m] = (n0 + m < N) ? B[(size_t)(n0 + m) * K + k0 + kk] : 0.f;
        }
        __syncthreads();
#pragma unroll
        for (int k = 0; k < 16; k++) {
            float4 a4 = *(const float4*)&As[k][(tid & 15) * 4];
            float4 b4 = *(const float4*)&Bs[k][(tid >> 4) * 4];
            float a[4] = {a4.x, a4.y, a4.z, a4.w};
            float b[4] = {b4.x, b4.y, b4.z, b4.w};
#pragma unroll
            for (int i = 0; i < 4; i++)
#pragma unroll
                for (int j = 0; j < 4; j++) c[i][j] = fmaf(a[i], b[j], c[i][j]);
        }
    }
    int tm = m0 + (tid & 15) * 4, tn = n0 + (tid >> 4) * 4;
#pragma unroll
    for (int i = 0; i < 4; i++) {
        if (tm + i >= M) continue;
#pragma unroll
        for (int j = 0; j < 4; j++) {
            if (tn + j >= N) continue;
            float v = c[i][j] + bias[tn + j];
            if (TANH) v = tanhf(v);
            C[(size_t)(tm + i) * N + tn + j] = v;
        }
    }
}

// ---------------- GRU step: gh = h @ W_hh^T, gates, h1 ----------------------
// grid 128 CTAs (4 cols each), 256 threads: thread = (c=tid&3, b=tid>>2)
__global__ void k_gru(const float* __restrict__ Whh, const float* __restrict__ bhh, int t) {
    __shared__ float hs[64][65];
    __shared__ float ws[12][65];
    int tid = threadIdx.x;
    int c = tid & 3, b = tid >> 2;
    int col0 = blockIdx.x * 4;
    int col = col0 + c;
    const float* hprev = g_h1 + (size_t)((t > 0 ? t - 1 : 0) * BATCH) * HID;

    float ar = 0.f, az = 0.f, an = 0.f;
    for (int k0 = 0; k0 < HID; k0 += 64) {
        __syncthreads();
        for (int i = tid; i < 64 * 64; i += 256) {
            int bb = i >> 6, k = i & 63;
            hs[bb][k] = (t > 0) ? hprev[(size_t)bb * HID + k0 + k] : 0.f;
        }
        for (int i = tid; i < 12 * 64; i += 256) {
            int r_ = i >> 6, k = i & 63;
            int g = r_ >> 2, cc = r_ & 3;
            ws[r_][k] = Whh[(size_t)(g * HID + col0 + cc) * HID + k0 + k];
        }
        __syncthreads();
#pragma unroll 8
        for (int k = 0; k < 64; k++) {
            float hv = hs[b][k];
            ar = fmaf(hv, ws[c][k], ar);
            az = fmaf(hv, ws[4 + c][k], az);
            an = fmaf(hv, ws[8 + c][k], an);
        }
    }
    size_t base = (size_t)(t * BATCH + b) * G3;
    float gir = g_gi[base + col];
    float giz = g_gi[base + 512 + col];
    float gin = g_gi[base + 1024 + col];
    float r = 1.f / (1.f + expf(-(gir + ar + bhh[col])));
    float z = 1.f / (1.f + expf(-(giz + az + bhh[512 + col])));
    float n = tanhf(gin + r * (an + bhh[1024 + col]));
    float hp = (t > 0) ? hprev[(size_t)b * HID + col] : 0.f;
    g_h1[(size_t)(t * BATCH + b) * HID + col] = (1.f - z) * n + z * hp;
}

// ---------------- x = h1 * ct (ct broadcast over T) -------------------------
__global__ void k_xmul() {
    int i = blockIdx.x * 256 + threadIdx.x;        // grid 4096 -> 1048576
    int row = i >> 9, d = i & 511;
    g_x[i] = g_h1[i] * g_ct[(row & 63) * HID + d];
}

// ---------------- per-row 8-head self attention -----------------------------
__global__ void k_attn() {
    __shared__ float qs[512], ks[512], vs[512], sc[64], ex[64];
    int row = blockIdx.x, tid = threadIdx.x;       // 64 threads
    size_t base = (size_t)row * HID;
#pragma unroll
    for (int j = 0; j < 8; j++) {
        int idx = tid + 64 * j;
        qs[idx] = g_q[base + idx];
        ks[idx] = g_k[base + idx];
        vs[idx] = g_v[base + idx];
    }
    __syncthreads();
    int h = tid >> 3, g = tid & 7;
    float s = 0.f;
#pragma unroll 16
    for (int d = 0; d < 64; d++) s = fmaf(qs[h * 64 + d], ks[g * 64 + d], s);
    s *= (1.f / 64.f);
    sc[tid] = s;
    __syncthreads();
    float mx = sc[h * 8];
#pragma unroll
    for (int gg = 1; gg < 8; gg++) mx = fmaxf(mx, sc[h * 8 + gg]);
    float e = expf(s - mx);
    ex[tid] = e;
    __syncthreads();
    float den = 0.f;
#pragma unroll
    for (int gg = 0; gg < 8; gg++) den += ex[h * 8 + gg];
    float w = e / den;
    __syncthreads();
    sc[tid] = w;                                    // reuse sc for weights
    __syncthreads();
#pragma unroll
    for (int j = 0; j < 8; j++) {
        int idx = tid + 64 * j;
        int hh = idx >> 6, d = idx & 63;
        float o = 0.f;
#pragma unroll
        for (int gg = 0; gg < 8; gg++) o = fmaf(sc[hh * 8 + gg], vs[gg * 64 + d], o);
        g_att[base + idx] = o;
    }
}

// ---------------- big out GEMM (f32x2 packed): exp(logit@Wout^T+b) + partial sums
// 128x128 tile, 256 threads, 8x8 micro, K=512
__global__ __launch_bounds__(256) void k_outgemm(const float* __restrict__ Wout,
                                                 const float* __restrict__ bout,
                                                 float* __restrict__ out) {
    __shared__ float As[16][132];
    __shared__ float Bs[16][132];
    int n0 = blockIdx.x * 128, m0 = blockIdx.y * 128;
    int tid = threadIdx.x;
    int kk = tid & 15, rr = tid >> 4;
    u64 acc[8][4] = {};

    for (int k0 = 0; k0 < DIN; k0 += 16) {
        __syncthreads();
#pragma unroll
        for (int p = 0; p < 8; p++) {
            int m = rr + p * 16;
            As[kk][m] = g_logit[(size_t)(m0 + m) * DIN + k0 + kk];
            Bs[kk][m] = Wout[(size_t)(n0 + m) * DIN + k0 + kk];
        }
        __syncthreads();
#pragma unroll
        for (int k = 0; k < 16; k++) {
            const float* ap = &As[k][(tid & 15) * 8];
            float4 a0 = *(const float4*)ap;
            float4 a1 = *(const float4*)(ap + 4);
            const ulonglong2* bp = (const ulonglong2*)&Bs[k][(tid >> 4) * 8];
            ulonglong2 b01 = bp[0], b23 = bp[1];
            u64 bq[4] = {b01.x, b01.y, b23.x, b23.y};
            float a[8] = {a0.x, a0.y, a0.z, a0.w, a1.x, a1.y, a1.z, a1.w};
#pragma unroll
            for (int i = 0; i < 8; i++) {
                u64 ad = f2pack(a[i], a[i]);
#pragma unroll
                for (int j = 0; j < 4; j++) acc[i][j] = ffma2(ad, bq[j], acc[i][j]);
            }
        }
    }
    __syncthreads();
    float* sums = &As[0][0];                        // reuse smem: [128][16]
    int tmb = (tid & 15) * 8, tnb = (tid >> 4) * 8, tcol = tid >> 4;
    float4 bo0 = *(const float4*)&bout[n0 + tnb];
    float4 bo1 = *(const float4*)&bout[n0 + tnb + 4];
    float bo[8] = {bo0.x, bo0.y, bo0.z, bo0.w, bo1.x, bo1.y, bo1.z, bo1.w};
#pragma unroll
    for (int i = 0; i < 8; i++) {
        float cvals[8];
#pragma unroll
        for (int j = 0; j < 4; j++) f2unpack(acc[i][j], cvals[2 * j], cvals[2 * j + 1]);
        float e[8], ps = 0.f;
#pragma unroll
        for (int j = 0; j < 8; j++) {
            e[j] = expf(cvals[j] + bo[j]);
            ps += e[j];
        }
        int row = m0 + tmb + i;
        float4* o = (float4*)(out + (size_t)row * VOCAB + n0 + tnb);
        o[0] = make_float4(e[0], e[1], e[2], e[3]);
        o[1] = make_float4(e[4], e[5], e[6], e[7]);
        sums[(tmb + i) * 16 + tcol] = ps;
    }
    __syncthreads();
    if (tid < 128) {
        float s = 0.f;
#pragma unroll
        for (int c2 = 0; c2 < 16; c2++) s += sums[tid * 16 + c2];
        g_part[(size_t)(m0 + tid) * NT_G5 + blockIdx.x] = s;
    }
}

// ---------------- normalize rows of out by summed partials ------------------
__global__ void k_norm(float* __restrict__ out) {
    __shared__ float red[256];
    int row = blockIdx.x, tid = threadIdx.x;
    float s = 0.f;
    for (int j = tid; j < NT_G5; j += 256) s += g_part[(size_t)row * NT_G5 + j];
    red[tid] = s;
    __syncthreads();
    for (int off = 128; off > 0; off >>= 1) {
        if (tid < off) red[tid] += red[tid + off];
        __syncthreads();
    }
    float inv = 1.f / red[0];
    float4* o = (float4*)(out + (size_t)row * VOCAB);
    for (int j = tid; j < VOCAB / 4; j += 256) {
        float4 v = o[j];
        v.x *= inv; v.y *= inv; v.z *= inv; v.w *= inv;
        o[j] = v;
    }
}

// ---------------- launch ----------------------------------------------------
extern "C" void kernel_launch(void* const* d_in, const int* in_sizes, int n_in,
                              void* d_out, int out_size) {
    const int*   y     = (const int*)d_in[0];
    const float* ctx   = (const float*)d_in[1];   // [1,64,768]
    const float* embW  = (const float*)d_in[2];   // [V,512]
    const float* W_ih  = (const float*)d_in[3];   // [1536,512]
    const float* b_ih  = (const float*)d_in[4];
    const float* W_hh  = (const float*)d_in[5];   // [1536,512]
    const float* b_hh  = (const float*)d_in[6];
    const float* W_att = (const float*)d_in[7];   // [512,768]
    const float* b_att = (const float*)d_in[8];
    const float* Wq    = (const float*)d_in[9];
    const float* bq    = (const float*)d_in[10];
    const float* Wk    = (const float*)d_in[11];
    const float* bk    = (const float*)d_in[12];
    const float* Wv    = (const float*)d_in[13];
    const float* bv    = (const float*)d_in[14];
    const float* Wfc   = (const float*)d_in[15];
    const float* bfc   = (const float*)d_in[16];
    const float* Wh2o  = (const float*)d_in[17];  // [512,512]
    const float* bh2o  = (const float*)d_in[18];
    const float* Wout  = (const float*)d_in[19];  // [32000,512]
    const float* bout  = (const float*)d_in[20];
    float* out = (float*)d_out;

    float* p_yemb;  cudaGetSymbolAddress((void**)&p_yemb,  g_yemb);
    float* p_ct;    cudaGetSymbolAddress((void**)&p_ct,    g_ct);
    float* p_gi;    cudaGetSymbolAddress((void**)&p_gi,    g_gi);
    float* p_x;     cudaGetSymbolAddress((void**)&p_x,     g_x);
    float* p_q;     cudaGetSymbolAddress((void**)&p_q,     g_q);
    float* p_k;     cudaGetSymbolAddress((void**)&p_k,     g_k);
    float* p_v;     cudaGetSymbolAddress((void**)&p_v,     g_v);
    float* p_att;   cudaGetSymbolAddress((void**)&p_att,   g_att);
    float* p_h2;    cudaGetSymbolAddress((void**)&p_h2,    g_h2);
    float* p_logit; cudaGetSymbolAddress((void**)&p_logit, g_logit);

    // 1. embedding gather
    k_gather<<<TB, 128>>>(y, embW);
    // 2. ct = tanh(ctx @ W_att^T + b_att)   [64,512], K=768
    k_gemm_nt<true><<<dim3(8, 1), 256>>>(ctx, W_att, b_att, p_ct, BATCH, HID, FEAT);
    // 3. gi = yemb @ W_ih^T + b_ih          [2048,1536], K=512
    k_gemm_nt<false><<<dim3(24, 32), 256>>>(p_yemb, W_ih, b_ih, p_gi, TB, G3, DIN);
    // 4. GRU recurrence
    for (int t = 0; t < T_STEPS; t++) k_gru<<<128, 256>>>(W_hh, b_hh, t);
    // 5. x = h1 * ct
    k_xmul<<<4096, 256>>>();
    // 6. q, k, v projections                [2048,512], K=512
    k_gemm_nt<false><<<dim3(8, 32), 256>>>(p_x, Wq, bq, p_q, TB, HID, HID);
    k_gemm_nt<false><<<dim3(8, 32), 256>>>(p_x, Wk, bk, p_k, TB, HID, HID);
    k_gemm_nt<false><<<dim3(8, 32), 256>>>(p_x, Wv, bv, p_v, TB, HID, HID);
    // 7. attention
    k_attn<<<TB, 64>>>();
    // 8. h2 = att @ Wfc^T + bfc
    k_gemm_nt<false><<<dim3(8, 32), 256>>>(p_att, Wfc, bfc, p_h2, TB, HID, HID);
    // 9. logit = tanh(h2 @ Wh2o^T + bh2o)
    k_gemm_nt<true><<<dim3(8, 32), 256>>>(p_h2, Wh2o, bh2o, p_logit, TB, DIN, HID);
    // 10. out = exp(logit @ Wout^T + bout), per-tile row sums
    k_outgemm<<<dim3(NT_G5, 16), 256>>>(Wout, bout, out);
    // 11. normalize rows -> softmax probs
    k_norm<<<TB, 256>>>(out);
    (void)in_sizes; (void)n_in; (void)out_size;
}

// round 15
// speedup vs baseline: 1.7851x; 1.7851x over previous
#include <cuda_runtime.h>
#include <cuda_bf16.h>
#include <math.h>

// ---------------- problem dims ----------------
#define T_STEPS 32
#define BATCH   64
#define TB      2048
#define DIN     512
#define HID     512
#define G3      1536
#define FEAT    768
#define VOCAB   32000
#define NCTA_GRU 128

typedef unsigned long long u64;
typedef unsigned int u32;
typedef unsigned short u16;

// ---------------- scratch ----------------
__device__ u16   g_yembb[TB * DIN];          // bf16 embedding rows
__device__ float g_ct[BATCH * HID];
__device__ float g_gi[TB * G3];
__device__ float g_h1[TB * HID];
__device__ u16   g_xb[TB * HID];             // bf16 x = h1*ct
__device__ float g_q[TB * HID];
__device__ float g_k[TB * HID];
__device__ float g_v[TB * HID];
__device__ u16   g_attb[TB * HID];           // bf16 attention out
__device__ u16   g_h2b[TB * HID];            // bf16 h2
__device__ u16   g_logitb[TB * DIN];         // bf16 logit
__device__ u16   g_wihb[G3 * DIN];
__device__ u16   g_wqb[HID * HID];
__device__ u16   g_wkb[HID * HID];
__device__ u16   g_wvb[HID * HID];
__device__ u16   g_wfcb[HID * HID];
__device__ u16   g_wh2ob[DIN * HID];
__device__ u16   g_woutb[VOCAB * DIN];
__device__ float g_rowsum[TB];
__device__ unsigned int g_bar[T_STEPS];

// ---------------- helpers ----------------
__device__ __forceinline__ u64 f2pack(float x, float y) {
    u64 r; asm("mov.b64 %0, {%1, %2};" : "=l"(r) : "f"(x), "f"(y)); return r;
}
__device__ __forceinline__ void f2unpack(u64 p, float& x, float& y) {
    asm("mov.b64 {%0, %1}, %2;" : "=f"(x), "=f"(y) : "l"(p));
}
__device__ __forceinline__ u64 ffma2(u64 a, u64 b, u64 c) {
    u64 d; asm("fma.rn.f32x2 %0, %1, %2, %3;" : "=l"(d) : "l"(a), "l"(b), "l"(c)); return d;
}
__device__ __forceinline__ u16 f2bf(float x) {
    __nv_bfloat16 h = __float2bfloat16_rn(x);
    return *(u16*)&h;
}

// ---------------- embedding gather -> bf16 ----------------
__global__ void k_gather(const int* __restrict__ y, const float* __restrict__ embW) {
    int row = blockIdx.x;
    int yi  = y[row];
    const float4* src = (const float4*)(embW + (size_t)yi * DIN);
    float4 v = src[threadIdx.x];
    ushort4 o = { f2bf(v.x), f2bf(v.y), f2bf(v.z), f2bf(v.w) };
    ((ushort4*)(g_yembb + (size_t)row * DIN))[threadIdx.x] = o;
}

// ---------------- fp32 -> bf16 weight conversion ----------------
__global__ void k_cvt(const float* __restrict__ src, u16* __restrict__ dst) {
    int i = blockIdx.x * 256 + threadIdx.x;
    float4 v = ((const float4*)src)[i];
    ushort4 o = { f2bf(v.x), f2bf(v.y), f2bf(v.z), f2bf(v.w) };
    ((ushort4*)dst)[i] = o;
}

// ---------------- fp32 SIMT GEMM (only for small ct) ----------------
template <bool TANH>
__global__ void k_gemm_nt(const float* __restrict__ A, const float* __restrict__ B,
                          const float* __restrict__ bias, float* __restrict__ C,
                          int M, int N, int K) {
    __shared__ float As[16][68];
    __shared__ float Bs[16][68];
    int m0 = blockIdx.y * 64, n0 = blockIdx.x * 64;
    int tid = threadIdx.x;
    int kk = tid & 15, rr = tid >> 4;
    float c[4][4] = {};
    for (int k0 = 0; k0 < K; k0 += 16) {
        __syncthreads();
#pragma unroll
        for (int p = 0; p < 4; p++) {
            int m = rr + p * 16;
            As[kk][m] = (m0 + m < M) ? A[(size_t)(m0 + m) * K + k0 + kk] : 0.f;
            Bs[kk][m] = (n0 + m < N) ? B[(size_t)(n0 + m) * K + k0 + kk] : 0.f;
        }
        __syncthreads();
#pragma unroll
        for (int k = 0; k < 16; k++) {
            float4 a4 = *(const float4*)&As[k][(tid & 15) * 4];
            float4 b4 = *(const float4*)&Bs[k][(tid >> 4) * 4];
            float a[4] = {a4.x, a4.y, a4.z, a4.w};
            float b[4] = {b4.x, b4.y, b4.z, b4.w};
#pragma unroll
            for (int i = 0; i < 4; i++)
#pragma unroll
                for (int j = 0; j < 4; j++) c[i][j] = fmaf(a[i], b[j], c[i][j]);
        }
    }
    int tm = m0 + (tid & 15) * 4, tn = n0 + (tid >> 4) * 4;
#pragma unroll
    for (int i = 0; i < 4; i++) {
        if (tm + i >= M) continue;
#pragma unroll
        for (int j = 0; j < 4; j++) {
            if (tn + j >= N) continue;
            float v = c[i][j] + bias[tn + j];
            if (TANH) v = tanhf(v);
            C[(size_t)(tm + i) * N + tn + j] = v;
        }
    }
}

// ---------------- persistent GRU: all 32 steps, one kernel ------------------
__global__ __launch_bounds__(256) void k_gru_persist(const float* __restrict__ Whh,
                                                     const float* __restrict__ bhh) {
    __shared__ __align__(16) float ws[12][516];
    __shared__ __align__(16) float hs[64][68];
    int tid = threadIdx.x;
    int c = tid & 3, b = tid >> 2;
    int col0 = blockIdx.x * 4;
    int col  = col0 + c;

    for (int i = tid; i < 12 * 512; i += 256) {
        int r_ = i >> 9, k = i & 511;
        int gate = r_ >> 2, cc = r_ & 3;
        ws[r_][k] = Whh[(size_t)(gate * HID + col0 + cc) * HID + k];
    }
    float br = bhh[col], bz = bhh[512 + col], bn = bhh[1024 + col];
    __syncthreads();

    for (int t = 0; t < T_STEPS; t++) {
        u64 ar2 = 0, az2 = 0, an2 = 0;
        if (t > 0) {
            const float* hprev = g_h1 + (size_t)(t - 1) * BATCH * HID;
            for (int k0 = 0; k0 < HID; k0 += 64) {
                __syncthreads();
                for (int i = tid; i < 1024; i += 256) {
                    int bb = i >> 4, kq = i & 15;
                    *(float4*)&hs[bb][kq * 4] =
                        *(const float4*)&hprev[(size_t)bb * HID + k0 + kq * 4];
                }
                __syncthreads();
#pragma unroll 4
                for (int kk = 0; kk < 64; kk += 4) {
                    float4 h4 = *(const float4*)&hs[b][kk];
                    u64 h01 = f2pack(h4.x, h4.y), h23 = f2pack(h4.z, h4.w);
                    float4 w4;
                    w4 = *(const float4*)&ws[c][k0 + kk];
                    ar2 = ffma2(h01, f2pack(w4.x, w4.y), ar2);
                    ar2 = ffma2(h23, f2pack(w4.z, w4.w), ar2);
                    w4 = *(const float4*)&ws[4 + c][k0 + kk];
                    az2 = ffma2(h01, f2pack(w4.x, w4.y), az2);
                    az2 = ffma2(h23, f2pack(w4.z, w4.w), az2);
                    w4 = *(const float4*)&ws[8 + c][k0 + kk];
                    an2 = ffma2(h01, f2pack(w4.x, w4.y), an2);
                    an2 = ffma2(h23, f2pack(w4.z, w4.w), an2);
                }
            }
        }
        float arx, ary, azx, azy, anx, any_;
        f2unpack(ar2, arx, ary); f2unpack(az2, azx, azy); f2unpack(an2, anx, any_);
        float ar = arx + ary, az = azx + azy, an = anx + any_;

        size_t gib = (size_t)(t * BATCH + b) * G3;
        float gir = g_gi[gib + col];
        float giz = g_gi[gib + 512 + col];
        float gin = g_gi[gib + 1024 + col];
        float r = 1.f / (1.f + __expf(-(gir + ar + br)));
        float z = 1.f / (1.f + __expf(-(giz + az + bz)));
        float n = tanhf(gin + r * (an + bn));
        float hp = (t > 0) ? g_h1[(size_t)((t - 1) * BATCH + b) * HID + col] : 0.f;
        g_h1[(size_t)(t * BATCH + b) * HID + col] = (1.f - z) * n + z * hp;

        if (t < T_STEPS - 1) {
            __threadfence();
            __syncthreads();
            if (tid == 0) {
                atomicAdd(&g_bar[t], 1u);
                while (atomicAdd(&g_bar[t], 0u) < (unsigned)NCTA_GRU) {}
            }
            __syncthreads();
        }
    }
}

// ---------------- x = h1 * ct -> bf16 ----------------
__global__ void k_xmul() {
    int i = (blockIdx.x * 256 + threadIdx.x) * 2;       // grid 2048
    int row = i >> 9, d = i & 511;
    const float* ctp = g_ct + (row & 63) * HID + d;
    float a0 = g_h1[i] * ctp[0];
    float a1 = g_h1[i + 1] * ctp[1];
    u32 p = (u32)f2bf(a0) | ((u32)f2bf(a1) << 16);
    *(u32*)&g_xb[i] = p;
}

// ---------------- per-row 8-head self attention (bf16 out) ------------------
__global__ void k_attn() {
    __shared__ float qs[512], ks[512], vs[512], sc[64], ex[64];
    int row = blockIdx.x, tid = threadIdx.x;
    size_t base = (size_t)row * HID;
#pragma unroll
    for (int j = 0; j < 8; j++) {
        int idx = tid + 64 * j;
        qs[idx] = g_q[base + idx];
        ks[idx] = g_k[base + idx];
        vs[idx] = g_v[base + idx];
    }
    __syncthreads();
    int h = tid >> 3, g = tid & 7;
    float s = 0.f;
#pragma unroll 16
    for (int d = 0; d < 64; d++) s = fmaf(qs[h * 64 + d], ks[g * 64 + d], s);
    s *= (1.f / 64.f);
    sc[tid] = s;
    __syncthreads();
    float mx = sc[h * 8];
#pragma unroll
    for (int gg = 1; gg < 8; gg++) mx = fmaxf(mx, sc[h * 8 + gg]);
    float e = expf(s - mx);
    ex[tid] = e;
    __syncthreads();
    float den = 0.f;
#pragma unroll
    for (int gg = 0; gg < 8; gg++) den += ex[h * 8 + gg];
    float w = e / den;
    __syncthreads();
    sc[tid] = w;
    __syncthreads();
#pragma unroll
    for (int j = 0; j < 8; j++) {
        int idx = tid + 64 * j;
        int hh = idx >> 6, d = idx & 63;
        float o = 0.f;
#pragma unroll
        for (int gg = 0; gg < 8; gg++) o = fmaf(sc[hh * 8 + gg], vs[gg * 64 + d], o);
        g_attb[base + idx] = f2bf(o);
    }
}

// ---------------- bf16 MMA helper ----------------
__device__ __forceinline__ void mma16816(float* c, const u32* a, const u32* b) {
    asm volatile(
        "mma.sync.aligned.m16n8k16.row.col.f32.bf16.bf16.f32 "
        "{%0,%1,%2,%3}, {%4,%5,%6,%7}, {%8,%9}, {%0,%1,%2,%3};"
        : "+f"(c[0]), "+f"(c[1]), "+f"(c[2]), "+f"(c[3])
        : "r"(a[0]), "r"(a[1]), "r"(a[2]), "r"(a[3]), "r"(b[0]), "r"(b[1]));
}

// ---------------- generic bf16 tensor-core GEMM, K=512 ----------------------
// C[M,N] = act(A[M,512] @ B[N,512]^T + bias). CTA 128x128, 8 warps (2m x 4n).
template <bool TANH, bool OUTB16>
__global__ __launch_bounds__(256) void k_gemm_bf16(const u16* __restrict__ Ab,
                                                   const u16* __restrict__ Bb,
                                                   const float* __restrict__ bias,
                                                   void* __restrict__ Cout, int N) {
    __shared__ __align__(16) u16 As[128][72];
    __shared__ __align__(16) u16 Bs[128][72];
    int tid = threadIdx.x;
    int m0 = blockIdx.y * 128, n0 = blockIdx.x * 128;
    int warp = tid >> 5, lane = tid & 31;
    int wm = (warp >> 2) * 64, wn = (warp & 3) * 32;
    int g = lane >> 2, kt = lane & 3;
    float c[4][4][4] = {};

    for (int k0 = 0; k0 < DIN; k0 += 64) {
        __syncthreads();
#pragma unroll
        for (int p = 0; p < 4; p++) {
            int j = tid + 256 * p;
            int row = j >> 3, q = j & 7;
            *(uint4*)&As[row][q * 8] =
                *(const uint4*)(Ab + (size_t)(m0 + row) * DIN + k0 + q * 8);
            *(uint4*)&Bs[row][q * 8] =
                *(const uint4*)(Bb + (size_t)(n0 + row) * DIN + k0 + q * 8);
        }
        __syncthreads();
#pragma unroll
        for (int kk = 0; kk < 4; kk++) {
            int kb = kk * 16;
            u32 a[4][4], bq[4][2];
#pragma unroll
            for (int mt = 0; mt < 4; mt++) {
                int row = wm + mt * 16 + g;
                a[mt][0] = *(const u32*)&As[row][kb + kt * 2];
                a[mt][1] = *(const u32*)&As[row + 8][kb + kt * 2];
                a[mt][2] = *(const u32*)&As[row][kb + kt * 2 + 8];
                a[mt][3] = *(const u32*)&As[row + 8][kb + kt * 2 + 8];
            }
#pragma unroll
            for (int nt = 0; nt < 4; nt++) {
                int rn = wn + nt * 8 + g;
                bq[nt][0] = *(const u32*)&Bs[rn][kb + kt * 2];
                bq[nt][1] = *(const u32*)&Bs[rn][kb + kt * 2 + 8];
            }
#pragma unroll
            for (int mt = 0; mt < 4; mt++)
#pragma unroll
                for (int nt = 0; nt < 4; nt++)
                    mma16816(c[mt][nt], a[mt], bq[nt]);
        }
    }

    float bo[4][2];
#pragma unroll
    for (int nt = 0; nt < 4; nt++) {
        int gcol = n0 + wn + nt * 8 + kt * 2;
        bo[nt][0] = bias[gcol];
        bo[nt][1] = bias[gcol + 1];
    }
#pragma unroll
    for (int mt = 0; mt < 4; mt++) {
#pragma unroll
        for (int i = 0; i < 2; i++) {
            int row = m0 + wm + mt * 16 + g + 8 * i;
#pragma unroll
            for (int nt = 0; nt < 4; nt++) {
                int gcol = n0 + wn + nt * 8 + kt * 2;
                float v0 = c[mt][nt][i * 2 + 0] + bo[nt][0];
                float v1 = c[mt][nt][i * 2 + 1] + bo[nt][1];
                if (TANH) { v0 = tanhf(v0); v1 = tanhf(v1); }
                if (OUTB16) {
                    u32 p = (u32)f2bf(v0) | ((u32)f2bf(v1) << 16);
                    *(u32*)&((u16*)Cout)[(size_t)row * N + gcol] = p;
                } else {
                    *(float2*)&((float*)Cout)[(size_t)row * N + gcol] =
                        make_float2(v0, v1);
                }
            }
        }
    }
}

// ---------------- bf16 out GEMM + fused exp/rowsum --------------------------
__global__ __launch_bounds__(256) void k_outgemm_bf16(const u16* __restrict__ Ab,
                                                      const u16* __restrict__ Bb,
                                                      const float* __restrict__ bout,
                                                      float* __restrict__ out) {
    __shared__ __align__(16) u16 As[128][72];
    __shared__ __align__(16) u16 Bs[128][72];
    __shared__ float rsum[128];
    int tid = threadIdx.x;
    int m0 = blockIdx.y * 128, n0 = blockIdx.x * 128;
    int warp = tid >> 5, lane = tid & 31;
    int wm = (warp >> 2) * 64, wn = (warp & 3) * 32;
    int g = lane >> 2, kt = lane & 3;
    float c[4][4][4] = {};
    if (tid < 128) rsum[tid] = 0.f;

    for (int k0 = 0; k0 < DIN; k0 += 64) {
        __syncthreads();
#pragma unroll
        for (int p = 0; p < 4; p++) {
            int j = tid + 256 * p;
            int row = j >> 3, q = j & 7;
            *(uint4*)&As[row][q * 8] =
                *(const uint4*)(Ab + (size_t)(m0 + row) * DIN + k0 + q * 8);
            *(uint4*)&Bs[row][q * 8] =
                *(const uint4*)(Bb + (size_t)(n0 + row) * DIN + k0 + q * 8);
        }
        __syncthreads();
#pragma unroll
        for (int kk = 0; kk < 4; kk++) {
            int kb = kk * 16;
            u32 a[4][4], bq[4][2];
#pragma unroll
            for (int mt = 0; mt < 4; mt++) {
                int row = wm + mt * 16 + g;
                a[mt][0] = *(const u32*)&As[row][kb + kt * 2];
                a[mt][1] = *(const u32*)&As[row + 8][kb + kt * 2];
                a[mt][2] = *(const u32*)&As[row][kb + kt * 2 + 8];
                a[mt][3] = *(const u32*)&As[row + 8][kb + kt * 2 + 8];
            }
#pragma unroll
            for (int nt = 0; nt < 4; nt++) {
                int rn = wn + nt * 8 + g;
                bq[nt][0] = *(const u32*)&Bs[rn][kb + kt * 2];
                bq[nt][1] = *(const u32*)&Bs[rn][kb + kt * 2 + 8];
            }
#pragma unroll
            for (int mt = 0; mt < 4; mt++)
#pragma unroll
                for (int nt = 0; nt < 4; nt++)
                    mma16816(c[mt][nt], a[mt], bq[nt]);
        }
    }

    float bo[4][2];
#pragma unroll
    for (int nt = 0; nt < 4; nt++) {
        int gcol = n0 + wn + nt * 8 + kt * 2;
        bo[nt][0] = bout[gcol];
        bo[nt][1] = bout[gcol + 1];
    }
#pragma unroll
    for (int mt = 0; mt < 4; mt++) {
#pragma unroll
        for (int i = 0; i < 2; i++) {
            int lrow = wm + mt * 16 + g + 8 * i;
            int grow = m0 + lrow;
            float rs = 0.f;
#pragma unroll
            for (int nt = 0; nt < 4; nt++) {
                float e0 = __expf(c[mt][nt][i * 2 + 0] + bo[nt][0]);
                float e1 = __expf(c[mt][nt][i * 2 + 1] + bo[nt][1]);
                rs += e0 + e1;
                int gcol = n0 + wn + nt * 8 + kt * 2;
                *(float2*)&out[(size_t)grow * VOCAB + gcol] = make_float2(e0, e1);
            }
            atomicAdd(&rsum[lrow], rs);
        }
    }
    __syncthreads();
    if (tid < 128) atomicAdd(&g_rowsum[m0 + tid], rsum[tid]);
}

// ---------------- normalize ----------------
__global__ void k_norm(float* __restrict__ out, const float* __restrict__ rowsum) {
    int row = blockIdx.x, tid = threadIdx.x;
    float inv = 1.f / rowsum[row];
    float4* o = (float4*)(out + (size_t)row * VOCAB);
    for (int j = tid; j < VOCAB / 4; j += 256) {
        float4 v = o[j];
        v.x *= inv; v.y *= inv; v.z *= inv; v.w *= inv;
        o[j] = v;
    }
}

// ---------------- launch ----------------
extern "C" void kernel_launch(void* const* d_in, const int* in_sizes, int n_in,
                              void* d_out, int out_size) {
    const int*   y     = (const int*)d_in[0];
    const float* ctx   = (const float*)d_in[1];
    const float* embW  = (const float*)d_in[2];
    const float* W_ih  = (const float*)d_in[3];
    const float* b_ih  = (const float*)d_in[4];
    const float* W_hh  = (const float*)d_in[5];
    const float* b_hh  = (const float*)d_in[6];
    const float* W_att = (const float*)d_in[7];
    const float* b_att = (const float*)d_in[8];
    const float* Wq    = (const float*)d_in[9];
    const float* bq    = (const float*)d_in[10];
    const float* Wk    = (const float*)d_in[11];
    const float* bk    = (const float*)d_in[12];
    const float* Wv    = (const float*)d_in[13];
    const float* bv    = (const float*)d_in[14];
    const float* Wfc   = (const float*)d_in[15];
    const float* bfc   = (const float*)d_in[16];
    const float* Wh2o  = (const float*)d_in[17];
    const float* bh2o  = (const float*)d_in[18];
    const float* Wout  = (const float*)d_in[19];
    const float* bout  = (const float*)d_in[20];
    float* out = (float*)d_out;

    float* p_ct;    cudaGetSymbolAddress((void**)&p_ct,    g_ct);
    float* p_gi;    cudaGetSymbolAddress((void**)&p_gi,    g_gi);
    float* p_q;     cudaGetSymbolAddress((void**)&p_q,     g_q);
    float* p_k;     cudaGetSymbolAddress((void**)&p_k,     g_k);
    float* p_v;     cudaGetSymbolAddress((void**)&p_v,     g_v);
    u16* p_yembb;   cudaGetSymbolAddress((void**)&p_yembb, g_yembb);
    u16* p_xb;      cudaGetSymbolAddress((void**)&p_xb,    g_xb);
    u16* p_attb;    cudaGetSymbolAddress((void**)&p_attb,  g_attb);
    u16* p_h2b;     cudaGetSymbolAddress((void**)&p_h2b,   g_h2b);
    u16* p_logitb;  cudaGetSymbolAddress((void**)&p_logitb, g_logitb);
    u16* p_wihb;    cudaGetSymbolAddress((void**)&p_wihb,  g_wihb);
    u16* p_wqb;     cudaGetSymbolAddress((void**)&p_wqb,   g_wqb);
    u16* p_wkb;     cudaGetSymbolAddress((void**)&p_wkb,   g_wkb);
    u16* p_wvb;     cudaGetSymbolAddress((void**)&p_wvb,   g_wvb);
    u16* p_wfcb;    cudaGetSymbolAddress((void**)&p_wfcb,  g_wfcb);
    u16* p_wh2ob;   cudaGetSymbolAddress((void**)&p_wh2ob, g_wh2ob);
    u16* p_woutb;   cudaGetSymbolAddress((void**)&p_woutb, g_woutb);
    float* p_rowsum; cudaGetSymbolAddress((void**)&p_rowsum, g_rowsum);
    void*  p_bar;    cudaGetSymbolAddress(&p_bar, g_bar);

    cudaMemsetAsync(p_bar, 0, T_STEPS * sizeof(unsigned int));
    cudaMemsetAsync(p_rowsum, 0, TB * sizeof(float));

    // weight conversions (independent; front-loaded to overlap)
    k_cvt<<<G3 * DIN / 1024, 256>>>(W_ih, p_wihb);
    k_cvt<<<HID * HID / 1024, 256>>>(Wq, p_wqb);
    k_cvt<<<HID * HID / 1024, 256>>>(Wk, p_wkb);
    k_cvt<<<HID * HID / 1024, 256>>>(Wv, p_wvb);
    k_cvt<<<HID * HID / 1024, 256>>>(Wfc, p_wfcb);
    k_cvt<<<DIN * HID / 1024, 256>>>(Wh2o, p_wh2ob);
    k_cvt<<<VOCAB * DIN / 1024, 256>>>(Wout, p_woutb);
    // embedding gather -> bf16
    k_gather<<<TB, 128>>>(y, embW);
    // ct = tanh(ctx @ W_att^T)  (fp32 SIMT, tiny)
    k_gemm_nt<true><<<dim3(8, 1), 256>>>(ctx, W_att, b_att, p_ct, BATCH, HID, FEAT);
    // gi = yemb @ W_ih^T + b_ih  (bf16 MMA, fp32 out)
    k_gemm_bf16<false, false><<<dim3(G3 / 128, TB / 128), 256>>>(p_yembb, p_wihb, b_ih, p_gi, G3);
    // GRU recurrence (persistent)
    k_gru_persist<<<NCTA_GRU, 256>>>(W_hh, b_hh);
    // x = h1 * ct -> bf16
    k_xmul<<<TB * HID / 512, 256>>>();
    // q, k, v (bf16 MMA, fp32 out)
    k_gemm_bf16<false, false><<<dim3(HID / 128, TB / 128), 256>>>(p_xb, p_wqb, bq, p_q, HID);
    k_gemm_bf16<false, false><<<dim3(HID / 128, TB / 128), 256>>>(p_xb, p_wkb, bk, p_k, HID);
    k_gemm_bf16<false, false><<<dim3(HID / 128, TB / 128), 256>>>(p_xb, p_wvb, bv, p_v, HID);
    // attention (bf16 out)
    k_attn<<<TB, 64>>>();
    // h2 = att @ Wfc^T  (bf16 out)
    k_gemm_bf16<false, true><<<dim3(HID / 128, TB / 128), 256>>>(p_attb, p_wfcb, bfc, p_h2b, HID);
    // logit = tanh(h2 @ Wh2o^T)  (bf16 out)
    k_gemm_bf16<true, true><<<dim3(DIN / 128, TB / 128), 256>>>(p_h2b, p_wh2ob, bh2o, p_logitb, DIN);
    // out = exp(logit @ Wout^T + bout) + row sums
    k_outgemm_bf16<<<dim3(VOCAB / 128, TB / 128), 256>>>(p_logitb, p_woutb, bout, out);
    // normalize
    k_norm<<<TB, 256>>>(out, p_rowsum);
    (void)in_sizes; (void)n_in; (void)out_size;
}

// round 17
// speedup vs baseline: 2.5072x; 1.4045x over previous
#include <cuda_runtime.h>
#include <cuda_bf16.h>
#include <math.h>

// ---------------- problem dims ----------------
#define T_STEPS 32
#define BATCH   64
#define TB      2048
#define DIN     512
#define HID     512
#define G3      1536
#define FEAT    768
#define VOCAB   32000
#define NCTA_GRU 128

typedef unsigned long long u64;
typedef unsigned int u32;
typedef unsigned short u16;

// ---------------- scratch ----------------
__device__ u16   g_yembb[TB * DIN];
__device__ float g_ct[BATCH * HID];
__device__ float g_gi[TB * G3];
__device__ float g_h1[TB * HID];
__device__ u16   g_xb[TB * HID];
__device__ float g_qkv[TB * G3];             // fused q|k|v fp32
__device__ float g_bqkv[G3];                 // fused bias
__device__ u16   g_attb[TB * HID];
__device__ u16   g_h2b[TB * HID];
__device__ u16   g_logitb[TB * DIN];
__device__ u16   g_wihb[G3 * DIN];
__device__ u16   g_wqkvb[3 * HID * HID];     // fused Wq|Wk|Wv bf16
__device__ u16   g_wfcb[HID * HID];
__device__ u16   g_wh2ob[DIN * HID];
__device__ u16   g_woutb[VOCAB * DIN];
__device__ float g_rowsum[TB];
__device__ unsigned int g_bar[T_STEPS];

// ---------------- helpers ----------------
__device__ __forceinline__ u64 f2pack(float x, float y) {
    u64 r; asm("mov.b64 %0, {%1, %2};" : "=l"(r) : "f"(x), "f"(y)); return r;
}
__device__ __forceinline__ void f2unpack(u64 p, float& x, float& y) {
    asm("mov.b64 {%0, %1}, %2;" : "=f"(x), "=f"(y) : "l"(p));
}
__device__ __forceinline__ u64 ffma2(u64 a, u64 b, u64 c) {
    u64 d; asm("fma.rn.f32x2 %0, %1, %2, %3;" : "=l"(d) : "l"(a), "l"(b), "l"(c)); return d;
}
__device__ __forceinline__ u16 f2bf(float x) {
    __nv_bfloat16 h = __float2bfloat16_rn(x);
    return *(u16*)&h;
}
__device__ __forceinline__ void cpasync16(void* smem, const void* gmem) {
    u32 s = (u32)__cvta_generic_to_shared(smem);
    asm volatile("cp.async.cg.shared.global [%0], [%1], 16;" :: "r"(s), "l"(gmem));
}
#define CP_COMMIT() asm volatile("cp.async.commit_group;" ::: "memory")
#define CP_WAIT1()  asm volatile("cp.async.wait_group 1;" ::: "memory")
#define CP_WAIT0()  asm volatile("cp.async.wait_group 0;" ::: "memory")

// ---------------- embedding gather -> bf16 ----------------
__global__ void k_gather(const int* __restrict__ y, const float* __restrict__ embW) {
    int row = blockIdx.x;
    int yi  = y[row];
    const float4* src = (const float4*)(embW + (size_t)yi * DIN);
    float4 v = src[threadIdx.x];
    ushort4 o = { f2bf(v.x), f2bf(v.y), f2bf(v.z), f2bf(v.w) };
    ((ushort4*)(g_yembb + (size_t)row * DIN))[threadIdx.x] = o;
}

// ---------------- fp32 -> bf16 weight conversion ----------------
__global__ void k_cvt(const float* __restrict__ src, u16* __restrict__ dst) {
    int i = blockIdx.x * 256 + threadIdx.x;
    float4 v = ((const float4*)src)[i];
    ushort4 o = { f2bf(v.x), f2bf(v.y), f2bf(v.z), f2bf(v.w) };
    ((ushort4*)dst)[i] = o;
}

// ---------------- fused qkv bias concat ----------------
__global__ void k_catbias(const float* __restrict__ bq, const float* __restrict__ bk,
                          const float* __restrict__ bv) {
    int i = blockIdx.x * 256 + threadIdx.x;   // grid 6
    float v = (i < 512) ? bq[i] : (i < 1024) ? bk[i - 512] : bv[i - 1024];
    g_bqkv[i] = v;
}

// ---------------- fp32 SIMT GEMM (only for small ct) ----------------
template <bool TANH>
__global__ void k_gemm_nt(const float* __restrict__ A, const float* __restrict__ B,
                          const float* __restrict__ bias, float* __restrict__ C,
                          int M, int N, int K) {
    __shared__ float As[16][68];
    __shared__ float Bs[16][68];
    int m0 = blockIdx.y * 64, n0 = blockIdx.x * 64;
    int tid = threadIdx.x;
    int kk = tid & 15, rr = tid >> 4;
    float c[4][4] = {};
    for (int k0 = 0; k0 < K; k0 += 16) {
        __syncthreads();
#pragma unroll
        for (int p = 0; p < 4; p++) {
            int m = rr + p * 16;
            As[kk][m] = (m0 + m < M) ? A[(size_t)(m0 + m) * K + k0 + kk] : 0.f;
            Bs[kk][m] = (n0 + m < N) ? B[(size_t)(n0 + m) * K + k0 + kk] : 0.f;
        }
        __syncthreads();
#pragma unroll
        for (int k = 0; k < 16; k++) {
            float4 a4 = *(const float4*)&As[k][(tid & 15) * 4];
            float4 b4 = *(const float4*)&Bs[k][(tid >> 4) * 4];
            float a[4] = {a4.x, a4.y, a4.z, a4.w};
            float b[4] = {b4.x, b4.y, b4.z, b4.w};
#pragma unroll
            for (int i = 0; i < 4; i++)
#pragma unroll
                for (int j = 0; j < 4; j++) c[i][j] = fmaf(a[i], b[j], c[i][j]);
        }
    }
    int tm = m0 + (tid & 15) * 4, tn = n0 + (tid >> 4) * 4;
#pragma unroll
    for (int i = 0; i < 4; i++) {
        if (tm + i >= M) continue;
#pragma unroll
        for (int j = 0; j < 4; j++) {
            if (tn + j >= N) continue;
            float v = c[i][j] + bias[tn + j];
            if (TANH) v = tanhf(v);
            C[(size_t)(tm + i) * N + tn + j] = v;
        }
    }
}

// ---------------- persistent GRU (unchanged, proven) ------------------------
__global__ __launch_bounds__(256) void k_gru_persist(const float* __restrict__ Whh,
                                                     const float* __restrict__ bhh) {
    __shared__ __align__(16) float ws[12][516];
    __shared__ __align__(16) float hs[64][68];
    int tid = threadIdx.x;
    int c = tid & 3, b = tid >> 2;
    int col0 = blockIdx.x * 4;
    int col  = col0 + c;

    for (int i = tid; i < 12 * 512; i += 256) {
        int r_ = i >> 9, k = i & 511;
        int gate = r_ >> 2, cc = r_ & 3;
        ws[r_][k] = Whh[(size_t)(gate * HID + col0 + cc) * HID + k];
    }
    float br = bhh[col], bz = bhh[512 + col], bn = bhh[1024 + col];
    __syncthreads();

    for (int t = 0; t < T_STEPS; t++) {
        u64 ar2 = 0, az2 = 0, an2 = 0;
        if (t > 0) {
            const float* hprev = g_h1 + (size_t)(t - 1) * BATCH * HID;
            for (int k0 = 0; k0 < HID; k0 += 64) {
                __syncthreads();
                for (int i = tid; i < 1024; i += 256) {
                    int bb = i >> 4, kq = i & 15;
                    *(float4*)&hs[bb][kq * 4] =
                        *(const float4*)&hprev[(size_t)bb * HID + k0 + kq * 4];
                }
                __syncthreads();
#pragma unroll 4
                for (int kk = 0; kk < 64; kk += 4) {
                    float4 h4 = *(const float4*)&hs[b][kk];
                    u64 h01 = f2pack(h4.x, h4.y), h23 = f2pack(h4.z, h4.w);
                    float4 w4;
                    w4 = *(const float4*)&ws[c][k0 + kk];
                    ar2 = ffma2(h01, f2pack(w4.x, w4.y), ar2);
                    ar2 = ffma2(h23, f2pack(w4.z, w4.w), ar2);
                    w4 = *(const float4*)&ws[4 + c][k0 + kk];
                    az2 = ffma2(h01, f2pack(w4.x, w4.y), az2);
                    az2 = ffma2(h23, f2pack(w4.z, w4.w), az2);
                    w4 = *(const float4*)&ws[8 + c][k0 + kk];
                    an2 = ffma2(h01, f2pack(w4.x, w4.y), an2);
                    an2 = ffma2(h23, f2pack(w4.z, w4.w), an2);
                }
            }
        }
        float arx, ary, azx, azy, anx, any_;
        f2unpack(ar2, arx, ary); f2unpack(az2, azx, azy); f2unpack(an2, anx, any_);
        float ar = arx + ary, az = azx + azy, an = anx + any_;

        size_t gib = (size_t)(t * BATCH + b) * G3;
        float gir = g_gi[gib + col];
        float giz = g_gi[gib + 512 + col];
        float gin = g_gi[gib + 1024 + col];
        float r = 1.f / (1.f + __expf(-(gir + ar + br)));
        float z = 1.f / (1.f + __expf(-(giz + az + bz)));
        float n = tanhf(gin + r * (an + bn));
        float hp = (t > 0) ? g_h1[(size_t)((t - 1) * BATCH + b) * HID + col] : 0.f;
        g_h1[(size_t)(t * BATCH + b) * HID + col] = (1.f - z) * n + z * hp;

        if (t < T_STEPS - 1) {
            __threadfence();
            __syncthreads();
            if (tid == 0) {
                atomicAdd(&g_bar[t], 1u);
                while (atomicAdd(&g_bar[t], 0u) < (unsigned)NCTA_GRU) {}
            }
            __syncthreads();
        }
    }
}

// ---------------- x = h1 * ct -> bf16 ----------------
__global__ void k_xmul() {
    int i = (blockIdx.x * 256 + threadIdx.x) * 2;
    int row = i >> 9, d = i & 511;
    const float* ctp = g_ct + (row & 63) * HID + d;
    float a0 = g_h1[i] * ctp[0];
    float a1 = g_h1[i + 1] * ctp[1];
    u32 p = (u32)f2bf(a0) | ((u32)f2bf(a1) << 16);
    *(u32*)&g_xb[i] = p;
}

// ---------------- attention: reads fused qkv ----------------
__global__ void k_attn() {
    __shared__ float qs[512], ks[512], vs[512], sc[64], ex[64];
    int row = blockIdx.x, tid = threadIdx.x;
    size_t base3 = (size_t)row * G3;
#pragma unroll
    for (int j = 0; j < 8; j++) {
        int idx = tid + 64 * j;
        qs[idx] = g_qkv[base3 + idx];
        ks[idx] = g_qkv[base3 + 512 + idx];
        vs[idx] = g_qkv[base3 + 1024 + idx];
    }
    __syncthreads();
    int h = tid >> 3, g = tid & 7;
    float s = 0.f;
#pragma unroll 16
    for (int d = 0; d < 64; d++) s = fmaf(qs[h * 64 + d], ks[g * 64 + d], s);
    s *= (1.f / 64.f);
    sc[tid] = s;
    __syncthreads();
    float mx = sc[h * 8];
#pragma unroll
    for (int gg = 1; gg < 8; gg++) mx = fmaxf(mx, sc[h * 8 + gg]);
    float e = expf(s - mx);
    ex[tid] = e;
    __syncthreads();
    float den = 0.f;
#pragma unroll
    for (int gg = 0; gg < 8; gg++) den += ex[h * 8 + gg];
    float w = e / den;
    __syncthreads();
    sc[tid] = w;
    __syncthreads();
#pragma unroll
    for (int j = 0; j < 8; j++) {
        int idx = tid + 64 * j;
        int hh = idx >> 6, d = idx & 63;
        float o = 0.f;
#pragma unroll
        for (int gg = 0; gg < 8; gg++) o = fmaf(sc[hh * 8 + gg], vs[gg * 64 + d], o);
        g_attb[(size_t)row * HID + idx] = f2bf(o);
    }
}

// ---------------- bf16 MMA helper ----------------
__device__ __forceinline__ void mma16816(float* c, const u32* a, const u32* b) {
    asm volatile(
        "mma.sync.aligned.m16n8k16.row.col.f32.bf16.bf16.f32 "
        "{%0,%1,%2,%3}, {%4,%5,%6,%7}, {%8,%9}, {%0,%1,%2,%3};"
        : "+f"(c[0]), "+f"(c[1]), "+f"(c[2]), "+f"(c[3])
        : "r"(a[0]), "r"(a[1]), "r"(a[2]), "r"(a[3]), "r"(b[0]), "r"(b[1]));
}

// K-chunk = 32 u16, 2-stage cp.async pipeline. smem: 2*2*128*40*2 = 40960 B.
#define NKC (DIN / 32)   // 16 chunks

__device__ __forceinline__ void g5_load(u16 (*S)[40], const u16* __restrict__ base,
                                        int m0, int k0, int tid) {
#pragma unroll
    for (int p = 0; p < 2; p++) {
        int slot = tid + 256 * p;          // 512 slots: 128 rows x 4 x 16B
        int row = slot >> 2, q = slot & 3;
        cpasync16(&S[row][q * 8], base + (size_t)(m0 + row) * DIN + k0 + q * 8);
    }
}

// ---------------- generic bf16 tensor-core GEMM, K=512, pipelined -----------
template <bool TANH, bool OUTB16>
__global__ __launch_bounds__(256) void k_gemm_bf16(const u16* __restrict__ Ab,
                                                   const u16* __restrict__ Bb,
                                                   const float* __restrict__ bias,
                                                   void* __restrict__ Cout, int N) {
    __shared__ __align__(16) u16 As[2][128][40];
    __shared__ __align__(16) u16 Bs[2][128][40];
    int tid = threadIdx.x;
    int m0 = blockIdx.y * 128, n0 = blockIdx.x * 128;
    int warp = tid >> 5, lane = tid & 31;
    int wm = (warp >> 2) * 64, wn = (warp & 3) * 32;
    int g = lane >> 2, kt = lane & 3;
    float c[4][4][4] = {};

    g5_load(As[0], Ab, m0, 0, tid);
    g5_load(Bs[0], Bb, n0, 0, tid);
    CP_COMMIT();

    for (int ks = 0; ks < NKC; ks++) {
        int cur = ks & 1;
        if (ks + 1 < NKC) {
            g5_load(As[cur ^ 1], Ab, m0, (ks + 1) * 32, tid);
            g5_load(Bs[cur ^ 1], Bb, n0, (ks + 1) * 32, tid);
            CP_COMMIT();
            CP_WAIT1();
        } else {
            CP_WAIT0();
        }
        __syncthreads();
#pragma unroll
        for (int kk = 0; kk < 2; kk++) {
            int kb = kk * 16;
            u32 a[4][4], bq[4][2];
#pragma unroll
            for (int mt = 0; mt < 4; mt++) {
                int row = wm + mt * 16 + g;
                a[mt][0] = *(const u32*)&As[cur][row][kb + kt * 2];
                a[mt][1] = *(const u32*)&As[cur][row + 8][kb + kt * 2];
                a[mt][2] = *(const u32*)&As[cur][row][kb + kt * 2 + 8];
                a[mt][3] = *(const u32*)&As[cur][row + 8][kb + kt * 2 + 8];
            }
#pragma unroll
            for (int nt = 0; nt < 4; nt++) {
                int rn = wn + nt * 8 + g;
                bq[nt][0] = *(const u32*)&Bs[cur][rn][kb + kt * 2];
                bq[nt][1] = *(const u32*)&Bs[cur][rn][kb + kt * 2 + 8];
            }
#pragma unroll
            for (int mt = 0; mt < 4; mt++)
#pragma unroll
                for (int nt = 0; nt < 4; nt++)
                    mma16816(c[mt][nt], a[mt], bq[nt]);
        }
        __syncthreads();
    }

    float bo[4][2];
#pragma unroll
    for (int nt = 0; nt < 4; nt++) {
        int gcol = n0 + wn + nt * 8 + kt * 2;
        bo[nt][0] = bias[gcol];
        bo[nt][1] = bias[gcol + 1];
    }
#pragma unroll
    for (int mt = 0; mt < 4; mt++) {
#pragma unroll
        for (int i = 0; i < 2; i++) {
            int row = m0 + wm + mt * 16 + g + 8 * i;
#pragma unroll
            for (int nt = 0; nt < 4; nt++) {
                int gcol = n0 + wn + nt * 8 + kt * 2;
                float v0 = c[mt][nt][i * 2 + 0] + bo[nt][0];
                float v1 = c[mt][nt][i * 2 + 1] + bo[nt][1];
                if (TANH) { v0 = tanhf(v0); v1 = tanhf(v1); }
                if (OUTB16) {
                    u32 p = (u32)f2bf(v0) | ((u32)f2bf(v1) << 16);
                    *(u32*)&((u16*)Cout)[(size_t)row * N + gcol] = p;
                } else {
                    *(float2*)&((float*)Cout)[(size_t)row * N + gcol] =
                        make_float2(v0, v1);
                }
            }
        }
    }
}

// ---------------- bf16 out GEMM + fused exp/rowsum, pipelined ---------------
__global__ __launch_bounds__(256) void k_outgemm_bf16(const u16* __restrict__ Ab,
                                                      const u16* __restrict__ Bb,
                                                      const float* __restrict__ bout,
                                                      float* __restrict__ out) {
    __shared__ __align__(16) u16 As[2][128][40];
    __shared__ __align__(16) u16 Bs[2][128][40];
    __shared__ float rsum[128];
    int tid = threadIdx.x;
    int m0 = blockIdx.y * 128, n0 = blockIdx.x * 128;
    int warp = tid >> 5, lane = tid & 31;
    int wm = (warp >> 2) * 64, wn = (warp & 3) * 32;
    int g = lane >> 2, kt = lane & 3;
    float c[4][4][4] = {};
    if (tid < 128) rsum[tid] = 0.f;

    g5_load(As[0], Ab, m0, 0, tid);
    g5_load(Bs[0], Bb, n0, 0, tid);
    CP_COMMIT();

    for (int ks = 0; ks < NKC; ks++) {
        int cur = ks & 1;
        if (ks + 1 < NKC) {
            g5_load(As[cur ^ 1], Ab, m0, (ks + 1) * 32, tid);
            g5_load(Bs[cur ^ 1], Bb, n0, (ks + 1) * 32, tid);
            CP_COMMIT();
            CP_WAIT1();
        } else {
            CP_WAIT0();
        }
        __syncthreads();
#pragma unroll
        for (int kk = 0; kk < 2; kk++) {
            int kb = kk * 16;
            u32 a[4][4], bq[4][2];
#pragma unroll
            for (int mt = 0; mt < 4; mt++) {
                int row = wm + mt * 16 + g;
                a[mt][0] = *(const u32*)&As[cur][row][kb + kt * 2];
                a[mt][1] = *(const u32*)&As[cur][row + 8][kb + kt * 2];
                a[mt][2] = *(const u32*)&As[cur][row][kb + kt * 2 + 8];
                a[mt][3] = *(const u32*)&As[cur][row + 8][kb + kt * 2 + 8];
            }
#pragma unroll
            for (int nt = 0; nt < 4; nt++) {
                int rn = wn + nt * 8 + g;
                bq[nt][0] = *(const u32*)&Bs[cur][rn][kb + kt * 2];
                bq[nt][1] = *(const u32*)&Bs[cur][rn][kb + kt * 2 + 8];
            }
#pragma unroll
            for (int mt = 0; mt < 4; mt++)
#pragma unroll
                for (int nt = 0; nt < 4; nt++)
                    mma16816(c[mt][nt], a[mt], bq[nt]);
        }
        __syncthreads();
    }

    float bo[4][2];
#pragma unroll
    for (int nt = 0; nt < 4; nt++) {
        int gcol = n0 + wn + nt * 8 + kt * 2;
        bo[nt][0] = bout[gcol];
        bo[nt][1] = bout[gcol + 1];
    }
#pragma unroll
    for (int mt = 0; mt < 4; mt++) {
#pragma unroll
        for (int i = 0; i < 2; i++) {
            int lrow = wm + mt * 16 + g + 8 * i;
            int grow = m0 + lrow;
            float rs = 0.f;
#pragma unroll
            for (int nt = 0; nt < 4; nt++) {
                float e0 = __expf(c[mt][nt][i * 2 + 0] + bo[nt][0]);
                float e1 = __expf(c[mt][nt][i * 2 + 1] + bo[nt][1]);
                rs += e0 + e1;
                int gcol = n0 + wn + nt * 8 + kt * 2;
                *(float2*)&out[(size_t)grow * VOCAB + gcol] = make_float2(e0, e1);
            }
            atomicAdd(&rsum[lrow], rs);
        }
    }
    __syncthreads();
    if (tid < 128) atomicAdd(&g_rowsum[m0 + tid], rsum[tid]);
}

// ---------------- normalize ----------------
__global__ void k_norm(float* __restrict__ out, const float* __restrict__ rowsum) {
    int row = blockIdx.x, tid = threadIdx.x;
    float inv = 1.f / rowsum[row];
    float4* o = (float4*)(out + (size_t)row * VOCAB);
    for (int j = tid; j < VOCAB / 4; j += 256) {
        float4 v = o[j];
        v.x *= inv; v.y *= inv; v.z *= inv; v.w *= inv;
        o[j] = v;
    }
}

// ---------------- launch ----------------
extern "C" void kernel_launch(void* const* d_in, const int* in_sizes, int n_in,
                              void* d_out, int out_size) {
    const int*   y     = (const int*)d_in[0];
    const float* ctx   = (const float*)d_in[1];
    const float* embW  = (const float*)d_in[2];
    const float* W_ih  = (const float*)d_in[3];
    const float* b_ih  = (const float*)d_in[4];
    const float* W_hh  = (const float*)d_in[5];
    const float* b_hh  = (const float*)d_in[6];
    const float* W_att = (const float*)d_in[7];
    const float* b_att = (const float*)d_in[8];
    const float* Wq    = (const float*)d_in[9];
    const float* bq    = (const float*)d_in[10];
    const float* Wk    = (const float*)d_in[11];
    const float* bk    = (const float*)d_in[12];
    const float* Wv    = (const float*)d_in[13];
    const float* bv    = (const float*)d_in[14];
    const float* Wfc   = (const float*)d_in[15];
    const float* bfc   = (const float*)d_in[16];
    const float* Wh2o  = (const float*)d_in[17];
    const float* bh2o  = (const float*)d_in[18];
    const float* Wout  = (const float*)d_in[19];
    const float* bout  = (const float*)d_in[20];
    float* out = (float*)d_out;

    float* p_ct;    cudaGetSymbolAddress((void**)&p_ct,    g_ct);
    float* p_gi;    cudaGetSymbolAddress((void**)&p_gi,    g_gi);
    float* p_qkv;   cudaGetSymbolAddress((void**)&p_qkv,   g_qkv);
    float* p_bqkv;  cudaGetSymbolAddress((void**)&p_bqkv,  g_bqkv);
    u16* p_yembb;   cudaGetSymbolAddress((void**)&p_yembb, g_yembb);
    u16* p_xb;      cudaGetSymbolAddress((void**)&p_xb,    g_xb);
    u16* p_attb;    cudaGetSymbolAddress((void**)&p_attb,  g_attb);
    u16* p_h2b;     cudaGetSymbolAddress((void**)&p_h2b,   g_h2b);
    u16* p_logitb;  cudaGetSymbolAddress((void**)&p_logitb, g_logitb);
    u16* p_wihb;    cudaGetSymbolAddress((void**)&p_wihb,  g_wihb);
    u16* p_wqkvb;   cudaGetSymbolAddress((void**)&p_wqkvb, g_wqkvb);
    u16* p_wfcb;    cudaGetSymbolAddress((void**)&p_wfcb,  g_wfcb);
    u16* p_wh2ob;   cudaGetSymbolAddress((void**)&p_wh2ob, g_wh2ob);
    u16* p_woutb;   cudaGetSymbolAddress((void**)&p_woutb, g_woutb);
    float* p_rowsum; cudaGetSymbolAddress((void**)&p_rowsum, g_rowsum);
    void*  p_bar;    cudaGetSymbolAddress(&p_bar, g_bar);

    cudaMemsetAsync(p_bar, 0, T_STEPS * sizeof(unsigned int));
    cudaMemsetAsync(p_rowsum, 0, TB * sizeof(float));

    // weight conversions (front-loaded)
    k_cvt<<<G3 * DIN / 1024, 256>>>(W_ih, p_wihb);
    k_cvt<<<HID * HID / 1024, 256>>>(Wq, p_wqkvb);
    k_cvt<<<HID * HID / 1024, 256>>>(Wk, p_wqkvb + HID * HID);
    k_cvt<<<HID * HID / 1024, 256>>>(Wv, p_wqkvb + 2 * HID * HID);
    k_cvt<<<HID * HID / 1024, 256>>>(Wfc, p_wfcb);
    k_cvt<<<DIN * HID / 1024, 256>>>(Wh2o, p_wh2ob);
    k_cvt<<<VOCAB * DIN / 1024, 256>>>(Wout, p_woutb);
    k_catbias<<<6, 256>>>(bq, bk, bv);
    // embedding gather -> bf16
    k_gather<<<TB, 128>>>(y, embW);
    // ct = tanh(ctx @ W_att^T)
    k_gemm_nt<true><<<dim3(8, 1), 256>>>(ctx, W_att, b_att, p_ct, BATCH, HID, FEAT);
    // gi = yemb @ W_ih^T + b_ih
    k_gemm_bf16<false, false><<<dim3(G3 / 128, TB / 128), 256>>>(p_yembb, p_wihb, b_ih, p_gi, G3);
    // GRU recurrence (persistent)
    k_gru_persist<<<NCTA_GRU, 256>>>(W_hh, b_hh);
    // x = h1 * ct -> bf16
    k_xmul<<<TB * HID / 512, 256>>>();
    // fused q|k|v GEMM
    k_gemm_bf16<false, false><<<dim3(G3 / 128, TB / 128), 256>>>(p_xb, p_wqkvb, p_bqkv, p_qkv, G3);
    // attention
    k_attn<<<TB, 64>>>();
    // h2 = att @ Wfc^T
    k_gemm_bf16<false, true><<<dim3(HID / 128, TB / 128), 256>>>(p_attb, p_wfcb, bfc, p_h2b, HID);
    // logit = tanh(h2 @ Wh2o^T)
    k_gemm_bf16<true, true><<<dim3(DIN / 128, TB / 128), 256>>>(p_h2b, p_wh2ob, bh2o, p_logitb, DIN);
    // out = exp(logit @ Wout^T + bout) + row sums
    k_outgemm_bf16<<<dim3(VOCAB / 128, TB / 128), 256>>>(p_logitb, p_woutb, bout, out);
    // normalize
    k_norm<<<TB, 256>>>(out, p_rowsum);
    (void)in_sizes; (void)n_in; (void)out_size;
}